// round 13
// baseline (speedup 1.0000x reference)
#include <cuda_runtime.h>
#include <math.h>
#include <stdint.h>

#define NN 32768
#define NE 65536

// ---------------- device scratch ----------------
__device__ float g_sum1[NN * 64];     // zeroed by node1 after consumption
__device__ float g_sum2[NN * 64];     // zeroed by node2 after consumption
__device__ float g_cnt [NN];          // zeroed by node2 after consumption
__device__ float g_h1  [NN * 64];
__device__ float g_h2  [NN * 64];
__device__ float g_he1 [NE * 64];     // relu(ea@W1a+b1a)
__device__ float g_he2 [NE * 64];     // relu(ea@W2a+b2a)
__device__ float g_Bt1 [4  * 4096];   // layer1 B chunks, vector-swizzled tf32
__device__ float g_Bt2 [65 * 4096];   // layer2 B chunks, vector-swizzled tf32

__device__ __forceinline__ float elu1(float v) { return v > 0.f ? v : expm1f(v); }

__device__ __forceinline__ float tf32r(float f) {
    uint32_t r;
    asm("cvt.rna.tf32.f32 %0, %1;" : "=r"(r) : "f"(f));
    return __uint_as_float(r);
}

__device__ __forceinline__ void mma8(float* c, const uint32_t* a, uint32_t b0, uint32_t b1) {
    asm volatile(
        "mma.sync.aligned.m16n8k8.row.col.f32.tf32.tf32.f32 "
        "{%0,%1,%2,%3}, {%4,%5,%6,%7}, {%8,%9}, {%0,%1,%2,%3};"
        : "+f"(c[0]), "+f"(c[1]), "+f"(c[2]), "+f"(c[3])
        : "r"(a[0]), "r"(a[1]), "r"(a[2]), "r"(a[3]), "r"(b0), "r"(b1));
}

#define CP_ASYNC16(dst_u32, src_ptr) \
    asm volatile("cp.async.cg.shared.global [%0], [%1], 16;" :: "r"(dst_u32), "l"(src_ptr))
#define CP_COMMIT()   asm volatile("cp.async.commit_group;")
#define CP_WAIT(n)    asm volatile("cp.async.wait_group %0;" :: "n"(n))

// B physical layout within a 4096-float chunk, for element (row i, col n):
//   q   = i & 3,  K(q) = (q&1) | ((q&2)<<1)
//   c16 = (n&7)*2 + (n>>5)          (16B-chunk index, 0..15)
//   nt  = (n>>3) & 3                (element within 16B)
//   phys = i*64 + ((c16 ^ K(q)) << 2) + nt
__device__ __forceinline__ int bphys(int i, int n) {
    int q = i & 3;
    int Kq = (q & 1) | ((q & 2) << 1);
    int c16 = (n & 7) * 2 + (n >> 5);
    return i * 64 + ((c16 ^ Kq) << 2) + ((n >> 3) & 3);
}

// ---------------- fused prep: he + btprep2 + btprep1 + cnt ----------------
__global__ __launch_bounds__(256) void prep_kernel(
    const int* __restrict__ ei, const float* __restrict__ ea,
    const float* __restrict__ W1a, const float* __restrict__ b1a,
    const float* __restrict__ W2a, const float* __restrict__ b2a,
    const float* __restrict__ W1b, const float* __restrict__ b1b,
    const float* __restrict__ W2b, const float* __restrict__ b2b)
{
    int b = blockIdx.x, t = threadIdx.x;
    if (b < 16384) {                                    // he: NE*64 threads
        int idx = b * 256 + t;
        int e = idx >> 6, c = idx & 63;
        float a0 = __ldg(&ea[e * 3]), a1 = __ldg(&ea[e * 3 + 1]), a2 = __ldg(&ea[e * 3 + 2]);
        float h1 = b1a[c] + a0 * W1a[c] + a1 * W1a[64 + c] + a2 * W1a[128 + c];
        float h2 = b2a[c] + a0 * W2a[c] + a1 * W2a[64 + c] + a2 * W2a[128 + c];
        g_he1[idx] = fmaxf(h1, 0.f);
        g_he2[idx] = fmaxf(h2, 0.f);
    } else if (b < 16384 + 1040) {                      // btprep2: 65*4096 threads
        int idx = (b - 16384) * 256 + t;
        int c = idx >> 12, r = idx & 4095, i = r >> 6, n = r & 63;
        float v = (c < 64) ? W2b[c * 4096 + r] : b2b[r];
        g_Bt2[c * 4096 + bphys(i, n)] = tf32r(v);
    } else if (b < 16384 + 1040 + 64) {                 // btprep1: 4*4096 threads
        int idx = (b - 16384 - 1040) * 256 + t;
        int c = idx >> 12, r = idx & 4095, k = r >> 6, n = r & 63;
        float v;
        if (c < 3) v = W1b[k * 192 + c * 64 + n];
        else       v = (k < 3) ? b1b[k * 64 + n] : 0.f;
        g_Bt1[c * 4096 + bphys(k, n)] = tf32r(v);
    } else {                                            // cnt: NE threads
        int e = (b - 16384 - 1040 - 64) * 256 + t;
        atomicAdd(&g_cnt[ei[NE + e]], 1.f);
    }
}

// ---------------- bilinear message GEMM via mma.sync tf32 ----------------
// D[m=edge 0..127][n=0..63] = sum over outer steps s of u[m,s] * (v[m,:] . B_s[:,n])
// Warp tile: 32m x 32n (8 warps). V in registers. B streams through a 4-buffer
// cp.async ring; TWO chunks per barrier phase (33 barriers instead of 65).
// LAYER2: u = he2[e] (+1 bias), v = h1[src]; S = 65
// LAYER1: u = x[src] (+1 bias), v = he1[e] (tail chunk: v = x padded); S = 4
template<int LAYER>
__global__ __launch_bounds__(256, 2) void bilinear_kernel(const int* __restrict__ ei,
                                                          const float* __restrict__ x)
{
    constexpr int S  = (LAYER == 1) ? 4 : 65;
    constexpr int PH = (S + 1) / 2;                 // phases of 2 chunks
    const float* Bt   = (LAYER == 1) ? g_Bt1  : g_Bt2;
    float*       osum = (LAYER == 1) ? g_sum1 : g_sum2;

    extern __shared__ float sm[];
    float* U  = sm;                        // [128][68]
    float* Bs = U + 128 * 68;              // [4][4096] ring (chunk c -> buf c&3)
    int*  srcs = (int*)(Bs + 4 * 4096);    // [128]
    int*  dsts = srcs + 128;               // [128]

    int t  = threadIdx.x;
    int e0 = blockIdx.x * 128;

    // prologue: issue chunks 0 and 1 as group G0
    #pragma unroll
    for (int j = 0; j < 4; ++j) {
        int fi = t * 4 + j;
        uint32_t d = (uint32_t)__cvta_generic_to_shared(Bs + fi * 4);
        CP_ASYNC16(d, Bt + fi * 4);
    }
    if (S > 1) {
        #pragma unroll
        for (int j = 0; j < 4; ++j) {
            int fi = t * 4 + j;
            uint32_t d = (uint32_t)__cvta_generic_to_shared(Bs + 4096 + fi * 4);
            CP_ASYNC16(d, Bt + 4096 + fi * 4);
        }
    }
    CP_COMMIT();

    if (t < 128) { srcs[t] = ei[e0 + t]; dsts[t] = ei[NE + e0 + t]; }
    __syncthreads();   // srcs visible

    // fill U [128][68] (tf32-rounded); visible to compute via phase-0 barrier
    if (LAYER == 2) {
        for (int idx = t; idx < 128 * 16; idx += 256) {
            int m = idx >> 4, q4 = idx & 15;
            float4 uu = __ldg((const float4*)(g_he2 + (e0 + m) * 64) + q4);
            uu.x = tf32r(uu.x); uu.y = tf32r(uu.y); uu.z = tf32r(uu.z); uu.w = tf32r(uu.w);
            *(float4*)(U + m * 68 + q4 * 4) = uu;
        }
        if (t < 128) U[t * 68 + 64] = 1.f;
    } else {
        if (t < 128) {
            const float* xp = x + srcs[t] * 3;
            U[t * 68 + 0] = tf32r(__ldg(xp));
            U[t * 68 + 1] = tf32r(__ldg(xp + 1));
            U[t * 68 + 2] = tf32r(__ldg(xp + 2));
            U[t * 68 + 3] = 1.f;
        }
    }

    int lane = t & 31, wid = t >> 5;
    int g = lane >> 2, q = lane & 3;
    int wm = wid >> 1, wn = wid & 1;
    int mb = wm * 32;
    int rows[4] = { mb + g, mb + g + 8, mb + 16 + g, mb + 24 + g };

    // V -> registers (invariant over s): v[r][j][tt] = V[rows[r]][q + 4tt + 8j]
    float v[4][8][2];
    #pragma unroll
    for (int r = 0; r < 4; ++r) {
        const float* p = (LAYER == 2) ? (g_h1 + srcs[rows[r]] * 64)
                                      : (g_he1 + (e0 + rows[r]) * 64);
        #pragma unroll
        for (int j = 0; j < 8; ++j)
            #pragma unroll
            for (int tt = 0; tt < 2; ++tt)
                v[r][j][tt] = tf32r(__ldg(p + q + 4 * tt + 8 * j));
    }
    float vt[4][2];   // layer1 tail-chunk A values (u=1, v=x padded)
    if (LAYER == 1) {
        #pragma unroll
        for (int r = 0; r < 4; ++r) {
            int sv = srcs[rows[r]];
            #pragma unroll
            for (int tt = 0; tt < 2; ++tt) {
                int c = q + 4 * tt;
                vt[r][tt] = (c < 3) ? tf32r(__ldg(x + sv * 3 + c)) : 0.f;
            }
        }
    }

    float cacc[2][4][4];
    #pragma unroll
    for (int a = 0; a < 2; ++a)
        #pragma unroll
        for (int b2 = 0; b2 < 4; ++b2)
            #pragma unroll
            for (int cx = 0; cx < 4; ++cx) cacc[a][b2][cx] = 0.f;

    int Kq = (q & 1) | ((q & 2) << 1);
    int cidx = ((g * 2 + wn) ^ Kq);   // float4 index within a row

    for (int p = 0; p < PH; ++p) {
        CP_WAIT(0);          // group for this phase's 2 chunks has landed
        __syncthreads();     // all warps done reading the buffers we now overwrite

        // issue next phase's loads (chunks 2p+2, 2p+3) into bufs (2p+2)&3,(2p+3)&3
        {
            int cA = 2 * p + 2;
            if (cA < S) {
                float* Bn = Bs + (cA & 3) * 4096;
                const float* gsrc = Bt + cA * 4096;
                #pragma unroll
                for (int j = 0; j < 4; ++j) {
                    int fi = t * 4 + j;
                    uint32_t d = (uint32_t)__cvta_generic_to_shared(Bn + fi * 4);
                    CP_ASYNC16(d, gsrc + fi * 4);
                }
            }
            int cB = 2 * p + 3;
            if (cB < S) {
                float* Bn = Bs + (cB & 3) * 4096;
                const float* gsrc = Bt + cB * 4096;
                #pragma unroll
                for (int j = 0; j < 4; ++j) {
                    int fi = t * 4 + j;
                    uint32_t d = (uint32_t)__cvta_generic_to_shared(Bn + fi * 4);
                    CP_ASYNC16(d, gsrc + fi * 4);
                }
            }
            CP_COMMIT();   // one group per phase (possibly empty)
        }

        // compute the 2 chunks of this phase
        #pragma unroll
        for (int ci = 0; ci < 2; ++ci) {
            int c = 2 * p + ci;
            if (c >= S) break;
            const float4* B4 = (const float4*)(Bs + (c & 3) * 4096);

            if (LAYER == 1 && c == S - 1) {
                uint32_t A0[4], A1[4];
                A0[0] = __float_as_uint(vt[0][0]); A0[1] = __float_as_uint(vt[1][0]);
                A0[2] = __float_as_uint(vt[0][1]); A0[3] = __float_as_uint(vt[1][1]);
                A1[0] = __float_as_uint(vt[2][0]); A1[1] = __float_as_uint(vt[3][0]);
                A1[2] = __float_as_uint(vt[2][1]); A1[3] = __float_as_uint(vt[3][1]);
                float4 f0 = B4[q * 16 + cidx];
                float4 f1 = B4[(q + 4) * 16 + cidx];
                const float* b0f = &f0.x;
                const float* b1f = &f1.x;
                #pragma unroll
                for (int nt = 0; nt < 4; ++nt) {
                    uint32_t b0 = __float_as_uint(b0f[nt]);
                    uint32_t b1 = __float_as_uint(b1f[nt]);
                    mma8(cacc[0][nt], A0, b0, b1);
                    mma8(cacc[1][nt], A1, b0, b1);
                }
            } else {
                float us0 = U[rows[0] * 68 + c];
                float us1 = U[rows[1] * 68 + c];
                float us2 = U[rows[2] * 68 + c];
                float us3 = U[rows[3] * 68 + c];
                #pragma unroll
                for (int j = 0; j < 8; ++j) {
                    float4 f0 = B4[(j * 8 + q) * 16 + cidx];
                    float4 f1 = B4[(j * 8 + q + 4) * 16 + cidx];
                    const float* b0f = &f0.x;
                    const float* b1f = &f1.x;
                    uint32_t A0[4], A1[4];
                    A0[0] = __float_as_uint(us0 * v[0][j][0]);
                    A0[1] = __float_as_uint(us1 * v[1][j][0]);
                    A0[2] = __float_as_uint(us0 * v[0][j][1]);
                    A0[3] = __float_as_uint(us1 * v[1][j][1]);
                    A1[0] = __float_as_uint(us2 * v[2][j][0]);
                    A1[1] = __float_as_uint(us3 * v[3][j][0]);
                    A1[2] = __float_as_uint(us2 * v[2][j][1]);
                    A1[3] = __float_as_uint(us3 * v[3][j][1]);
                    #pragma unroll
                    for (int nt = 0; nt < 4; ++nt) {
                        uint32_t b0 = __float_as_uint(b0f[nt]);
                        uint32_t b1 = __float_as_uint(b1f[nt]);
                        mma8(cacc[0][nt], A0, b0, b1);
                        mma8(cacc[1][nt], A1, b0, b1);
                    }
                }
            }
        }
    }

    // epilogue: scatter-add C fragments
    #pragma unroll
    for (int tile = 0; tile < 2; ++tile) {
        int dlo = dsts[rows[tile * 2]];
        int dhi = dsts[rows[tile * 2 + 1]];
        float* olo = osum + dlo * 64 + wn * 32 + 2 * q;
        float* ohi = osum + dhi * 64 + wn * 32 + 2 * q;
        #pragma unroll
        for (int nt = 0; nt < 4; ++nt) {
            atomicAdd(olo + nt * 8,     cacc[tile][nt][0]);
            atomicAdd(olo + nt * 8 + 1, cacc[tile][nt][1]);
            atomicAdd(ohi + nt * 8,     cacc[tile][nt][2]);
            atomicAdd(ohi + nt * 8 + 1, cacc[tile][nt][3]);
        }
    }
}

// ---------------- layer 1 node combine (self-cleaning g_sum1) ----------------
__global__ void node1_kernel(const float* __restrict__ x,
                             const float* __restrict__ root1,
                             const float* __restrict__ bias1)
{
    int idx = blockIdx.x * blockDim.x + threadIdx.x;   // NN*64 threads
    int n = idx >> 6, o = idx & 63;
    float c = fmaxf(g_cnt[n], 1.f);
    float ssum = g_sum1[idx];
    g_sum1[idx] = 0.f;                                 // reset for next replay
    float v = ssum / c + bias1[o]
            + x[n * 3 + 0] * root1[o]
            + x[n * 3 + 1] * root1[64 + o]
            + x[n * 3 + 2] * root1[128 + o];
    g_h1[idx] = elu1(v);
}

// ---------------- layer 2 node combine (self-cleaning g_sum2, g_cnt) ----------------
__global__ __launch_bounds__(256) void node2_kernel(
    const float* __restrict__ root2, const float* __restrict__ bias2)
{
    __shared__ float hs[4][64];
    int nb = blockIdx.x * 4;
    int t = threadIdx.x;
    int ln = t >> 6, o = t & 63;
    hs[ln][o] = g_h1[(nb + ln) * 64 + o];
    __syncthreads();
    int n = nb + ln;
    float acc = bias2[o];
    #pragma unroll 8
    for (int i = 0; i < 64; ++i)
        acc = fmaf(hs[ln][i], __ldg(&root2[i * 64 + o]), acc);
    float c = fmaxf(g_cnt[n], 1.f);
    float ssum = g_sum2[n * 64 + o];
    g_sum2[n * 64 + o] = 0.f;                          // reset for next replay
    acc += ssum / c;
    g_h2[n * 64 + o] = elu1(acc);
    __syncthreads();                                   // all g_cnt reads done
    if (o == 0) g_cnt[n] = 0.f;                        // reset for next replay
}

// ---------------- final FC ----------------
__global__ __launch_bounds__(256) void fc_kernel(
    const float* __restrict__ Wf, const float* __restrict__ bf,
    float* __restrict__ out)
{
    __shared__ float hs[2][64];
    int nb = blockIdx.x * 2;
    int t = threadIdx.x;
    int ln = t >> 7, o = t & 127;
    if (o < 64) hs[ln][o] = g_h2[(nb + ln) * 64 + o];
    __syncthreads();
    float acc = bf[o];
    #pragma unroll 8
    for (int i = 0; i < 64; ++i)
        acc = fmaf(hs[ln][i], __ldg(&Wf[i * 128 + o]), acc);
    out[(nb + ln) * 128 + o] = elu1(acc);
}

// ---------------- launch ----------------
#define SM_BYTES ((128 * 68 + 4 * 4096) * 4 + 256 * 4)

extern "C" void kernel_launch(void* const* d_in, const int* in_sizes, int n_in,
                              void* d_out, int out_size)
{
    const float* x     = (const float*)d_in[0];
    const int*   ei    = (const int*)d_in[1];
    const float* ea    = (const float*)d_in[2];
    const float* W1a   = (const float*)d_in[3];
    const float* b1a   = (const float*)d_in[4];
    const float* W1b   = (const float*)d_in[5];
    const float* b1b   = (const float*)d_in[6];
    const float* root1 = (const float*)d_in[7];
    const float* bias1 = (const float*)d_in[8];
    const float* W2a   = (const float*)d_in[9];
    const float* b2a   = (const float*)d_in[10];
    const float* W2b   = (const float*)d_in[11];
    const float* b2b   = (const float*)d_in[12];
    const float* root2 = (const float*)d_in[13];
    const float* bias2 = (const float*)d_in[14];
    const float* Wf    = (const float*)d_in[15];
    const float* bf    = (const float*)d_in[16];
    float*       out   = (float*)d_out;

    static int attr_done = 0;
    if (!attr_done) {
        cudaFuncSetAttribute(bilinear_kernel<1>, cudaFuncAttributeMaxDynamicSharedMemorySize, SM_BYTES);
        cudaFuncSetAttribute(bilinear_kernel<2>, cudaFuncAttributeMaxDynamicSharedMemorySize, SM_BYTES);
        attr_done = 1;
    }

    prep_kernel<<<16384 + 1040 + 64 + 256, 256>>>(ei, ea, W1a, b1a, W2a, b2a,
                                                  W1b, b1b, W2b, b2b);
    bilinear_kernel<1><<<NE / 128, 256, SM_BYTES>>>(ei, x);
    node1_kernel<<<NN * 64 / 256, 256>>>(x, root1, bias1);
    bilinear_kernel<2><<<NE / 128, 256, SM_BYTES>>>(ei, x);
    node2_kernel<<<NN / 4, 256>>>(root2, bias2);
    fc_kernel<<<NN / 2, 256>>>(Wf, bf, out);
}

// round 16
// speedup vs baseline: 1.4847x; 1.4847x over previous
#include <cuda_runtime.h>
#include <cuda_fp16.h>
#include <math.h>
#include <stdint.h>

#define NN 32768
#define NE 65536

// ---------------- device scratch ----------------
__device__ float g_sum1[NN * 64];     // zeroed by node1 after consumption
__device__ float g_sum2[NN * 64];     // zeroed by node2 after consumption
__device__ float g_cnt [NN];          // zeroed by node2 after consumption
__device__ float g_h1  [NN * 64];
__device__ float g_h2  [NN * 64];
__device__ float g_he1 [NE * 64];     // relu(ea@W1a+b1a)  (fp32)
__device__ float g_he2 [NE * 64];     // relu(ea@W2a+b2a)  (fp32)
__device__ uint32_t g_Bh1[4  * 2048]; // layer1 B chunks, fp16x2, vector-swizzled
__device__ uint32_t g_Bh2[65 * 2048]; // layer2 B chunks, fp16x2, vector-swizzled

__device__ __forceinline__ float elu1(float v) { return v > 0.f ? v : expm1f(v); }

// pack two fp32 -> fp16x2 (lo = first arg), round-to-nearest
__device__ __forceinline__ uint32_t f2h2(float lo, float hi) {
    uint32_t d;
    asm("cvt.rn.f16x2.f32 %0, %1, %2;" : "=r"(d) : "f"(hi), "f"(lo));
    return d;
}
__device__ __forceinline__ uint32_t hmul2(uint32_t a, uint32_t b) {
    uint32_t d;
    asm("mul.rn.f16x2 %0, %1, %2;" : "=r"(d) : "r"(a), "r"(b));
    return d;
}

__device__ __forceinline__ void mma16(float* c, uint32_t a0, uint32_t a1,
                                      uint32_t a2, uint32_t a3,
                                      uint32_t b0, uint32_t b1) {
    asm volatile(
        "mma.sync.aligned.m16n8k16.row.col.f32.f16.f16.f32 "
        "{%0,%1,%2,%3}, {%4,%5,%6,%7}, {%8,%9}, {%0,%1,%2,%3};"
        : "+f"(c[0]), "+f"(c[1]), "+f"(c[2]), "+f"(c[3])
        : "r"(a0), "r"(a1), "r"(a2), "r"(a3), "r"(b0), "r"(b1));
}

#define CP_ASYNC16(dst_u32, src_ptr) \
    asm volatile("cp.async.cg.shared.global [%0], [%1], 16;" :: "r"(dst_u32), "l"(src_ptr))
#define CP_COMMIT()   asm volatile("cp.async.commit_group;")
#define CP_WAIT(n)    asm volatile("cp.async.wait_group %0;" :: "n"(n))

// B physical layout within a 2048-word (fp16x2) chunk, element (k2-row, col n):
//   q   = k2 & 3,  K(q) = (q&1) | ((q&2)<<1)
//   c16 = (n&7)*2 + (n>>5); nt = (n>>3)&3
//   phys = k2*64 + ((c16 ^ K(q)) << 2) + nt      (word index; word = fp16x2 of k=2k2,2k2+1)
__device__ __forceinline__ int bphys16(int k2, int n) {
    int q = k2 & 3;
    int Kq = (q & 1) | ((q & 2) << 1);
    int c16 = (n & 7) * 2 + (n >> 5);
    return k2 * 64 + ((c16 ^ Kq) << 2) + ((n >> 3) & 3);
}

// ---------------- fused prep: he + bhprep2 + bhprep1 + cnt ----------------
__global__ __launch_bounds__(256) void prep_kernel(
    const int* __restrict__ ei, const float* __restrict__ ea,
    const float* __restrict__ W1a, const float* __restrict__ b1a,
    const float* __restrict__ W2a, const float* __restrict__ b2a,
    const float* __restrict__ W1b, const float* __restrict__ b1b,
    const float* __restrict__ W2b, const float* __restrict__ b2b)
{
    int b = blockIdx.x, t = threadIdx.x;
    if (b < 16384) {                                    // he: NE*64 threads
        int idx = b * 256 + t;
        int e = idx >> 6, c = idx & 63;
        float a0 = __ldg(&ea[e * 3]), a1 = __ldg(&ea[e * 3 + 1]), a2 = __ldg(&ea[e * 3 + 2]);
        float h1 = b1a[c] + a0 * W1a[c] + a1 * W1a[64 + c] + a2 * W1a[128 + c];
        float h2 = b2a[c] + a0 * W2a[c] + a1 * W2a[64 + c] + a2 * W2a[128 + c];
        g_he1[idx] = fmaxf(h1, 0.f);
        g_he2[idx] = fmaxf(h2, 0.f);
    } else if (b < 16384 + 520) {                       // bhprep2: 65*2048 words
        int idx = (b - 16384) * 256 + t;
        int c = idx >> 11, r = idx & 2047, k2 = r >> 6, n = r & 63;
        int i0 = 2 * k2, i1 = 2 * k2 + 1;
        float v0, v1;
        if (c < 64) { v0 = W2b[c * 4096 + i0 * 64 + n]; v1 = W2b[c * 4096 + i1 * 64 + n]; }
        else        { v0 = b2b[i0 * 64 + n];            v1 = b2b[i1 * 64 + n]; }
        g_Bh2[c * 2048 + bphys16(k2, n)] = f2h2(v0, v1);
    } else if (b < 16384 + 520 + 32) {                  // bhprep1: 4*2048 words
        int idx = (b - 16384 - 520) * 256 + t;
        int c = idx >> 11, r = idx & 2047, k2 = r >> 6, n = r & 63;
        int i0 = 2 * k2, i1 = 2 * k2 + 1;
        float v0, v1;
        if (c < 3) { v0 = W1b[i0 * 192 + c * 64 + n]; v1 = W1b[i1 * 192 + c * 64 + n]; }
        else {
            v0 = (i0 < 3) ? b1b[i0 * 64 + n] : 0.f;
            v1 = (i1 < 3) ? b1b[i1 * 64 + n] : 0.f;
        }
        g_Bh1[c * 2048 + bphys16(k2, n)] = f2h2(v0, v1);
    } else {                                            // cnt: NE threads
        int e = (b - 16384 - 520 - 32) * 256 + t;
        atomicAdd(&g_cnt[ei[NE + e]], 1.f);
    }
}

// ---------------- bilinear message GEMM via mma.sync fp16 (m16n8k16) ----------------
// D[m=edge 0..127][n=0..63] = sum over outer steps s of u[m,s] * (v[m,:] . B_s[:,n])
// Warp tile: 32m x 32n (8 warps). V in fp16x2 registers (32 regs). B streams as fp16
// through 3 x 8KB smem ring (cp.async), 1 barrier/chunk, conflict-free LDS.128.
// LAYER2: u = he2[e] (+1 bias), v = h1[src]; S = 65
// LAYER1: u = x[src] (+1 bias), v = he1[e] (tail chunk: A = x padded); S = 4
template<int LAYER>
__global__ __launch_bounds__(256, 2) void bilinear_kernel(const int* __restrict__ ei,
                                                          const float* __restrict__ x)
{
    constexpr int S = (LAYER == 1) ? 4 : 65;
    const uint32_t* Bt = (LAYER == 1) ? g_Bh1 : g_Bh2;
    float*        osum = (LAYER == 1) ? g_sum1 : g_sum2;

    extern __shared__ float sm[];
    float*    U  = sm;                         // [128][68] fp32 (raw u values)
    uint32_t* Bs = (uint32_t*)(U + 128 * 68);  // [3][2048] fp16x2 ring
    int*    srcs = (int*)(Bs + 3 * 2048);      // [128]
    int*    dsts = srcs + 128;                 // [128]

    int t  = threadIdx.x;
    int e0 = blockIdx.x * 128;

    // prefetch chunk 0 into buf 0 (8KB = 2 float4 per thread)
    #pragma unroll
    for (int j = 0; j < 2; ++j) {
        int fi = t * 2 + j;
        uint32_t d = (uint32_t)__cvta_generic_to_shared(Bs + fi * 4);
        CP_ASYNC16(d, (const char*)(Bt) + fi * 16);
    }
    CP_COMMIT();

    if (t < 128) { srcs[t] = ei[e0 + t]; dsts[t] = ei[NE + e0 + t]; }
    __syncthreads();   // srcs visible

    // fill U [128][68] raw fp32 (rounded to fp16 at consumption)
    if (LAYER == 2) {
        for (int idx = t; idx < 128 * 16; idx += 256) {
            int m = idx >> 4, q4 = idx & 15;
            float4 uu = __ldg((const float4*)(g_he2 + (e0 + m) * 64) + q4);
            *(float4*)(U + m * 68 + q4 * 4) = uu;
        }
        if (t < 128) U[t * 68 + 64] = 1.f;
    } else {
        if (t < 128) {
            const float* xp = x + srcs[t] * 3;
            U[t * 68 + 0] = __ldg(xp);
            U[t * 68 + 1] = __ldg(xp + 1);
            U[t * 68 + 2] = __ldg(xp + 2);
            U[t * 68 + 3] = 1.f;
        }
    }

    int lane = t & 31, wid = t >> 5;
    int g = lane >> 2, q = lane & 3;
    int wm = wid >> 1, wn = wid & 1;
    int mb = wm * 32;
    int rows[4] = { mb + g, mb + g + 8, mb + 16 + g, mb + 24 + g };

    // V -> fp16x2 registers (invariant over s):
    // v2[r][slab][h] = pack(v[rows[r]][slab*16 + 2q + 8h], v[...+1])
    uint32_t v2[4][4][2];
    #pragma unroll
    for (int r = 0; r < 4; ++r) {
        const float* p = (LAYER == 2) ? (g_h1 + srcs[rows[r]] * 64)
                                      : (g_he1 + (e0 + rows[r]) * 64);
        #pragma unroll
        for (int slab = 0; slab < 4; ++slab)
            #pragma unroll
            for (int h = 0; h < 2; ++h) {
                int i0 = slab * 16 + 2 * q + 8 * h;
                v2[r][slab][h] = f2h2(__ldg(p + i0), __ldg(p + i0 + 1));
            }
    }
    uint32_t vt2[4];   // layer1 tail-chunk A (k = 2q, 2q+1; zero for k>=3)
    if (LAYER == 1) {
        #pragma unroll
        for (int r = 0; r < 4; ++r) {
            int sv = srcs[rows[r]];
            float a = (2 * q     < 3) ? __ldg(x + sv * 3 + 2 * q)     : 0.f;
            float b = (2 * q + 1 < 3) ? __ldg(x + sv * 3 + 2 * q + 1) : 0.f;
            vt2[r] = f2h2(a, b);
        }
    }

    float cacc[2][4][4];
    #pragma unroll
    for (int a = 0; a < 2; ++a)
        #pragma unroll
        for (int b2 = 0; b2 < 4; ++b2)
            #pragma unroll
            for (int cx = 0; cx < 4; ++cx) cacc[a][b2][cx] = 0.f;

    int Kq = (q & 1) | ((q & 2) << 1);
    int cidx = ((g * 2 + wn) ^ Kq);   // uint4 index within a 16-uint4 row

    for (int s = 0; s < S; ++s) {
        if (s + 1 < S) {
            uint32_t* Bn = Bs + ((s + 1) % 3) * 2048;
            const char* gsrc = (const char*)(Bt + (s + 1) * 2048);
            #pragma unroll
            for (int j = 0; j < 2; ++j) {
                int fi = t * 2 + j;
                uint32_t d = (uint32_t)__cvta_generic_to_shared(Bn + fi * 4);
                CP_ASYNC16(d, gsrc + fi * 16);
            }
            CP_COMMIT();
            CP_WAIT(1);
        } else {
            CP_WAIT(0);
        }
        __syncthreads();   // single barrier per chunk (3-buffer WAR distance = 2)
        const uint4* B4 = (const uint4*)(Bs + (s % 3) * 2048);

        if (LAYER == 1 && s == S - 1) {
            // tail: slab 0 only, A = x padded (u = 1), upper-k halves are zero
            uint4 F0 = B4[q * 16 + cidx];
            uint4 F1 = B4[(q + 4) * 16 + cidx];
            const uint32_t* b0f = &F0.x;
            const uint32_t* b1f = &F1.x;
            #pragma unroll
            for (int nt = 0; nt < 4; ++nt) {
                mma16(cacc[0][nt], vt2[0], vt2[1], 0u, 0u, b0f[nt], b1f[nt]);
                mma16(cacc[1][nt], vt2[2], vt2[3], 0u, 0u, b0f[nt], b1f[nt]);
            }
        } else {
            uint32_t u2[4];
            #pragma unroll
            for (int r = 0; r < 4; ++r) {
                float us = U[rows[r] * 68 + s];
                u2[r] = f2h2(us, us);
            }
            #pragma unroll
            for (int slab = 0; slab < 4; ++slab) {
                uint4 F0 = B4[(slab * 8 + q) * 16 + cidx];
                uint4 F1 = B4[(slab * 8 + q + 4) * 16 + cidx];
                const uint32_t* b0f = &F0.x;
                const uint32_t* b1f = &F1.x;
                uint32_t a0t0 = hmul2(u2[0], v2[0][slab][0]);
                uint32_t a1t0 = hmul2(u2[1], v2[1][slab][0]);
                uint32_t a2t0 = hmul2(u2[0], v2[0][slab][1]);
                uint32_t a3t0 = hmul2(u2[1], v2[1][slab][1]);
                uint32_t a0t1 = hmul2(u2[2], v2[2][slab][0]);
                uint32_t a1t1 = hmul2(u2[3], v2[3][slab][0]);
                uint32_t a2t1 = hmul2(u2[2], v2[2][slab][1]);
                uint32_t a3t1 = hmul2(u2[3], v2[3][slab][1]);
                #pragma unroll
                for (int nt = 0; nt < 4; ++nt) {
                    mma16(cacc[0][nt], a0t0, a1t0, a2t0, a3t0, b0f[nt], b1f[nt]);
                    mma16(cacc[1][nt], a0t1, a1t1, a2t1, a3t1, b0f[nt], b1f[nt]);
                }
            }
        }
    }

    // epilogue: scatter-add C fragments (C layout of m16n8 unchanged vs k8)
    #pragma unroll
    for (int tile = 0; tile < 2; ++tile) {
        int dlo = dsts[rows[tile * 2]];
        int dhi = dsts[rows[tile * 2 + 1]];
        float* olo = osum + dlo * 64 + wn * 32 + 2 * q;
        float* ohi = osum + dhi * 64 + wn * 32 + 2 * q;
        #pragma unroll
        for (int nt = 0; nt < 4; ++nt) {
            atomicAdd(olo + nt * 8,     cacc[tile][nt][0]);
            atomicAdd(olo + nt * 8 + 1, cacc[tile][nt][1]);
            atomicAdd(ohi + nt * 8,     cacc[tile][nt][2]);
            atomicAdd(ohi + nt * 8 + 1, cacc[tile][nt][3]);
        }
    }
}

// ---------------- layer 1 node combine (self-cleaning g_sum1) ----------------
__global__ void node1_kernel(const float* __restrict__ x,
                             const float* __restrict__ root1,
                             const float* __restrict__ bias1)
{
    int idx = blockIdx.x * blockDim.x + threadIdx.x;   // NN*64 threads
    int n = idx >> 6, o = idx & 63;
    float c = fmaxf(g_cnt[n], 1.f);
    float ssum = g_sum1[idx];
    g_sum1[idx] = 0.f;                                 // reset for next replay
    float v = ssum / c + bias1[o]
            + x[n * 3 + 0] * root1[o]
            + x[n * 3 + 1] * root1[64 + o]
            + x[n * 3 + 2] * root1[128 + o];
    g_h1[idx] = elu1(v);
}

// ---------------- layer 2 node combine (self-cleaning g_sum2, g_cnt) ----------------
__global__ __launch_bounds__(256) void node2_kernel(
    const float* __restrict__ root2, const float* __restrict__ bias2)
{
    __shared__ float hs[4][64];
    int nb = blockIdx.x * 4;
    int t = threadIdx.x;
    int ln = t >> 6, o = t & 63;
    hs[ln][o] = g_h1[(nb + ln) * 64 + o];
    __syncthreads();
    int n = nb + ln;
    float acc = bias2[o];
    #pragma unroll 8
    for (int i = 0; i < 64; ++i)
        acc = fmaf(hs[ln][i], __ldg(&root2[i * 64 + o]), acc);
    float c = fmaxf(g_cnt[n], 1.f);
    float ssum = g_sum2[n * 64 + o];
    g_sum2[n * 64 + o] = 0.f;                          // reset for next replay
    acc += ssum / c;
    g_h2[n * 64 + o] = elu1(acc);
    __syncthreads();                                   // all g_cnt reads done
    if (o == 0) g_cnt[n] = 0.f;                        // reset for next replay
}

// ---------------- final FC ----------------
__global__ __launch_bounds__(256) void fc_kernel(
    const float* __restrict__ Wf, const float* __restrict__ bf,
    float* __restrict__ out)
{
    __shared__ float hs[2][64];
    int nb = blockIdx.x * 2;
    int t = threadIdx.x;
    int ln = t >> 7, o = t & 127;
    if (o < 64) hs[ln][o] = g_h2[(nb + ln) * 64 + o];
    __syncthreads();
    float acc = bf[o];
    #pragma unroll 8
    for (int i = 0; i < 64; ++i)
        acc = fmaf(hs[ln][i], __ldg(&Wf[i * 128 + o]), acc);
    out[(nb + ln) * 128 + o] = elu1(acc);
}

// ---------------- launch ----------------
#define SM_BYTES ((128 * 68 + 3 * 2048) * 4 + 256 * 4)

extern "C" void kernel_launch(void* const* d_in, const int* in_sizes, int n_in,
                              void* d_out, int out_size)
{
    const float* x     = (const float*)d_in[0];
    const int*   ei    = (const int*)d_in[1];
    const float* ea    = (const float*)d_in[2];
    const float* W1a   = (const float*)d_in[3];
    const float* b1a   = (const float*)d_in[4];
    const float* W1b   = (const float*)d_in[5];
    const float* b1b   = (const float*)d_in[6];
    const float* root1 = (const float*)d_in[7];
    const float* bias1 = (const float*)d_in[8];
    const float* W2a   = (const float*)d_in[9];
    const float* b2a   = (const float*)d_in[10];
    const float* W2b   = (const float*)d_in[11];
    const float* b2b   = (const float*)d_in[12];
    const float* root2 = (const float*)d_in[13];
    const float* bias2 = (const float*)d_in[14];
    const float* Wf    = (const float*)d_in[15];
    const float* bf    = (const float*)d_in[16];
    float*       out   = (float*)d_out;

    static int attr_done = 0;
    if (!attr_done) {
        cudaFuncSetAttribute(bilinear_kernel<1>, cudaFuncAttributeMaxDynamicSharedMemorySize, SM_BYTES);
        cudaFuncSetAttribute(bilinear_kernel<2>, cudaFuncAttributeMaxDynamicSharedMemorySize, SM_BYTES);
        attr_done = 1;
    }

    prep_kernel<<<16384 + 520 + 32 + 256, 256>>>(ei, ea, W1a, b1a, W2a, b2a,
                                                 W1b, b1b, W2b, b2b);
    bilinear_kernel<1><<<NE / 128, 256, SM_BYTES>>>(ei, x);
    node1_kernel<<<NN * 64 / 256, 256>>>(x, root1, bias1);
    bilinear_kernel<2><<<NE / 128, 256, SM_BYTES>>>(ei, x);
    node2_kernel<<<NN / 4, 256>>>(root2, bias2);
    fc_kernel<<<NN / 2, 256>>>(Wf, bf, out);
}